// round 1
// baseline (speedup 1.0000x reference)
#include <cuda_runtime.h>
#include <cstdint>

// StructAttentionLayer: B=16384, A=50, D=256, fp32.
//   e[b,a]   = attrs[b,a,:]·a_attr + entity[b,:]·a_ent
//   e        = leaky_relu(e, 0.2)
//   attn     = softmax_a(e) * A
//   out[b,:] = sum_a attn[b,a] * attrs[b,a,:]
//
// One CTA per b. 256 threads = 4 row-groups x 64 col-groups.
// Thread (rg, c) owns columns [4c, 4c+4) of rows {rg, rg+4, rg+8, ...} (<=13 rows),
// held in registers as float4 so attrs is read from HBM exactly once.

#define A_NUM 50
#define D_DIM 256
#define ALPHA 0.2f
#define NROWS 13   // ceil(50/4)

__global__ __launch_bounds__(256, 2)
void struct_attn_kernel(const float* __restrict__ attrs,
                        const float* __restrict__ ent,
                        const float* __restrict__ aa,
                        float* __restrict__ out)
{
    const int b    = blockIdx.x;
    const int t    = threadIdx.x;
    const int rg   = t >> 6;          // row group 0..3
    const int c    = t & 63;          // column group: cols 4c..4c+3
    const int warp = t >> 5;
    const int lane = t & 31;

    __shared__ float  ep[A_NUM + 2][2];   // per-row warp partials (+entity dot in row 50)
    __shared__ float  e_s[52];            // logits, then attention weights
    __shared__ float4 part[4][64];        // phase-3 row-group partials

    const float4* __restrict__ Arow =
        reinterpret_cast<const float4*>(attrs + (size_t)b * (A_NUM * D_DIM));

    // Weights for my 4 columns (aa is 2KB, stays in cache)
    const float4 aw = reinterpret_cast<const float4*>(aa)[c];          // a_attr
    // --- load my tile (<=13 float4 rows), front-batched LDG.128 ---
    float4 v[NROWS];
#pragma unroll
    for (int i = 0; i < NROWS; i++) {
        const int a = rg + 4 * i;
        v[i] = (a < A_NUM) ? Arow[a * (D_DIM / 4) + c]
                           : make_float4(0.f, 0.f, 0.f, 0.f);
    }

    // --- logits: e[a] partials. Each row reduced across the 32 lanes of one warp ---
#pragma unroll
    for (int i = 0; i < NROWS; i++) {
        const int a = rg + 4 * i;
        float s = v[i].x * aw.x + v[i].y * aw.y + v[i].z * aw.z + v[i].w * aw.w;
        s += __shfl_xor_sync(0xffffffffu, s, 16);
        s += __shfl_xor_sync(0xffffffffu, s, 8);
        s += __shfl_xor_sync(0xffffffffu, s, 4);
        s += __shfl_xor_sync(0xffffffffu, s, 2);
        s += __shfl_xor_sync(0xffffffffu, s, 1);
        if (lane == 0 && a < A_NUM) ep[a][warp & 1] = s;
    }

    // --- entity dot (row-group 0 only: warps 0 and 1 cover all 256 cols) ---
    if (rg == 0) {
        const float4 ew = reinterpret_cast<const float4*>(aa + D_DIM)[c];  // a_ent
        const float4 ev = reinterpret_cast<const float4*>(ent + (size_t)b * D_DIM)[c];
        float p = ev.x * ew.x + ev.y * ew.y + ev.z * ew.z + ev.w * ew.w;
        p += __shfl_xor_sync(0xffffffffu, p, 16);
        p += __shfl_xor_sync(0xffffffffu, p, 8);
        p += __shfl_xor_sync(0xffffffffu, p, 4);
        p += __shfl_xor_sync(0xffffffffu, p, 2);
        p += __shfl_xor_sync(0xffffffffu, p, 1);
        if (lane == 0) ep[A_NUM][warp] = p;
    }
    __syncthreads();

    // --- combine partials + leaky relu ---
    if (t < A_NUM) {
        const float ed = ep[A_NUM][0] + ep[A_NUM][1];
        float e = ep[t][0] + ep[t][1] + ed;
        e_s[t] = (e > 0.f) ? e : ALPHA * e;
    }
    __syncthreads();

    // --- softmax over 50 (warp 0), scaled by A_NUM ---
    if (warp == 0) {
        float x0 = e_s[lane];
        float x1 = (lane < A_NUM - 32) ? e_s[lane + 32] : -1e30f;
        float m = fmaxf(x0, x1);
        m = fmaxf(m, __shfl_xor_sync(0xffffffffu, m, 16));
        m = fmaxf(m, __shfl_xor_sync(0xffffffffu, m, 8));
        m = fmaxf(m, __shfl_xor_sync(0xffffffffu, m, 4));
        m = fmaxf(m, __shfl_xor_sync(0xffffffffu, m, 2));
        m = fmaxf(m, __shfl_xor_sync(0xffffffffu, m, 1));
        float q0 = __expf(x0 - m);
        float q1 = (lane < A_NUM - 32) ? __expf(x1 - m) : 0.f;
        float ssum = q0 + q1;
        ssum += __shfl_xor_sync(0xffffffffu, ssum, 16);
        ssum += __shfl_xor_sync(0xffffffffu, ssum, 8);
        ssum += __shfl_xor_sync(0xffffffffu, ssum, 4);
        ssum += __shfl_xor_sync(0xffffffffu, ssum, 2);
        ssum += __shfl_xor_sync(0xffffffffu, ssum, 1);
        const float inv = (float)A_NUM / ssum;
        e_s[lane] = q0 * inv;
        if (lane < A_NUM - 32) e_s[lane + 32] = q1 * inv;
    }
    __syncthreads();

    // --- weighted sum over my rows (all data still in registers) ---
    float4 acc = make_float4(0.f, 0.f, 0.f, 0.f);
#pragma unroll
    for (int i = 0; i < NROWS; i++) {
        const int a = rg + 4 * i;
        const float w = (a < A_NUM) ? e_s[a] : 0.f;
        acc.x += w * v[i].x;
        acc.y += w * v[i].y;
        acc.z += w * v[i].z;
        acc.w += w * v[i].w;
    }
    part[rg][c] = acc;
    __syncthreads();

    // --- combine 4 row-groups and store (threads 0..63, coalesced STG.128) ---
    if (t < 64) {
        const float4 p0 = part[0][t];
        const float4 p1 = part[1][t];
        const float4 p2 = part[2][t];
        const float4 p3 = part[3][t];
        float4 r;
        r.x = (p0.x + p1.x) + (p2.x + p3.x);
        r.y = (p0.y + p1.y) + (p2.y + p3.y);
        r.z = (p0.z + p1.z) + (p2.z + p3.z);
        r.w = (p0.w + p1.w) + (p2.w + p3.w);
        reinterpret_cast<float4*>(out + (size_t)b * D_DIM)[t] = r;
    }
}

extern "C" void kernel_launch(void* const* d_in, const int* in_sizes, int n_in,
                              void* d_out, int out_size)
{
    const float* attrs = (const float*)d_in[0];   // [16384, 50, 256]
    const float* ent   = (const float*)d_in[1];   // [16384, 256]
    const float* aa    = (const float*)d_in[2];   // [512, 1]
    float* out         = (float*)d_out;           // [16384, 256]

    const int B = in_sizes[1] / D_DIM;            // 16384
    struct_attn_kernel<<<B, 256>>>(attrs, ent, aa, out);
}